// round 3
// baseline (speedup 1.0000x reference)
#include <cuda_runtime.h>
#include <cuda_bf16.h>
#include <cmath>
#include <cstdint>
#include <cstring>
#include <complex>
#include <vector>
#include <algorithm>

// ============================================================================
// Sizes / constants
// ============================================================================
#define MAXN_AT 16384
#define MAXE_ED 262144
#define MAXNZ   3500
#define MAXG    96

// ============================================================================
// Device scratch (static: no allocations allowed)
// ============================================================================
__device__ float  g_sh[(size_t)MAXE_ED * 16];
__device__ float  g_basis[(size_t)MAXE_ED * 8];
__device__ int    g_sender[MAXE_ED];
__device__ unsigned char g_live[MAXE_ED];
__device__ int    g_count[MAXN_AT];
__device__ int    g_cursor[MAXN_AT];
__device__ int    g_offsets[MAXN_AT + 1];
__device__ float  g_embedded[(size_t)MAXN_AT * 1024];
__device__ float  g_inv[(size_t)MAXN_AT * 64];
__device__ float  g_atomE[MAXN_AT];

// Tables: uniform-access ones in __constant__, divergent-access ones in __device__
__constant__ float cWinv[128];           // (4,8,4)
__constant__ int   cCsStart[17];         // self-interaction, grouped by out slot
__constant__ short cCsI[MAXNZ];
__constant__ short cCsJ[MAXNZ];
__constant__ float cCsV[MAXNZ];
__constant__ int   cGn;
__constant__ short cGi[MAXG];
__constant__ short cGj[MAXG];
__constant__ float cGv[MAXG];
__device__ int   dTpStart[257];          // T assembly, grouped by p = o*16+si
__device__ short dCtA[MAXNZ];
__device__ float dCtV[MAXNZ];

// slot -> l map (compile-time foldable)
__host__ __device__ __forceinline__ constexpr int lof(int s) {
    return s == 0 ? 0 : (s < 4 ? 1 : (s < 9 ? 2 : 3));
}

// ============================================================================
// Edge geometry helpers
// ============================================================================
__device__ __forceinline__ void edge_geom(const float* pos, int s, int r,
                                          float& d, float& ux, float& uy, float& uz) {
    float dx = __ldg(pos + 3 * r + 0) - __ldg(pos + 3 * s + 0);
    float dy = __ldg(pos + 3 * r + 1) - __ldg(pos + 3 * s + 1);
    float dz = __ldg(pos + 3 * r + 2) - __ldg(pos + 3 * s + 2);
    d = sqrtf(dx * dx + dy * dy + dz * dz + 1e-12f);
    ux = dx / d; uy = dy / d; uz = dz / d;
}

__device__ __forceinline__ void make_sh(float x, float y, float z, float* Y) {
    Y[0] = 0.28209479177387814f;
    const float c1 = 0.4886025119029199f;
    Y[1] = c1 * y; Y[2] = c1 * z; Y[3] = c1 * x;
    Y[4] = 1.0925484305920792f * x * y;
    Y[5] = 1.0925484305920792f * y * z;
    Y[6] = 0.31539156525252005f * (3.0f * z * z - 1.0f);
    Y[7] = 1.0925484305920792f * x * z;
    Y[8] = 0.5462742152960396f * (x * x - y * y);
    Y[9]  = 0.5900435899266435f * y * (3.0f * x * x - y * y);
    Y[10] = 2.890611442640554f * x * y * z;
    Y[11] = 0.4570457994644658f * y * (5.0f * z * z - 1.0f);
    Y[12] = 0.3731763325901154f * z * (5.0f * z * z - 3.0f);
    Y[13] = 0.4570457994644658f * x * (5.0f * z * z - 1.0f);
    Y[14] = 1.445305721320277f * z * (x * x - y * y);
    Y[15] = 0.5900435899266435f * x * (x * x - 3.0f * y * y);
}

__device__ __forceinline__ void make_basis(float d, float* B) {
    float fc = 0.5f * (cosf(3.14159274101257324f * d / 5.0f) + 1.0f);
    #pragma unroll
    for (int i = 0; i < 8; i++) {
        float mu = (float)(5.0 * (double)i / 7.0);
        float t = (d - mu) / 0.625f;
        B[i] = expf(-0.5f * t * t) * fc;
    }
}

// ============================================================================
// Kernel 0: zero per-atom counts
// ============================================================================
__global__ void k_zero(int n) {
    int i = blockIdx.x * blockDim.x + threadIdx.x;
    if (i < n) g_count[i] = 0;
}

// ============================================================================
// Kernel 1: count live edges per receiver (+ record live flag)
// ============================================================================
__global__ void k_count(const float* __restrict__ pos, const int* __restrict__ snd,
                        const int* __restrict__ rcv, int E) {
    int e = blockIdx.x * blockDim.x + threadIdx.x;
    if (e >= E) return;
    int s = __ldg(snd + e), r = __ldg(rcv + e);
    float d, ux, uy, uz;
    edge_geom(pos, s, r, d, ux, uy, uz);
    unsigned char live = (d < 5.0f) ? 1 : 0;
    g_live[e] = live;
    if (live) atomicAdd(&g_count[r], 1);
}

// ============================================================================
// Kernel 2: exclusive scan of counts -> offsets, cursor  (single block)
// ============================================================================
__global__ void k_scan(int n) {
    __shared__ int part[1024];
    int tid = threadIdx.x;
    int chunk = (n + 1023) >> 10;
    int beg = tid * chunk, end = min(beg + chunk, n);
    int s = 0;
    for (int i = beg; i < end; i++) s += g_count[i];
    part[tid] = s;
    __syncthreads();
    for (int off = 1; off < 1024; off <<= 1) {
        int v = (tid >= off) ? part[tid - off] : 0;
        __syncthreads();
        part[tid] += v;
        __syncthreads();
    }
    int run = (tid == 0) ? 0 : part[tid - 1];
    for (int i = beg; i < end; i++) {
        g_offsets[i] = run;
        g_cursor[i] = run;
        run += g_count[i];
    }
    if (tid == 1023) g_offsets[n] = part[1023];
}

// ============================================================================
// Kernel 3: scatter live edges into receiver-sorted arrays (sh, basis, sender)
// ============================================================================
__global__ void k_scatter(const float* __restrict__ pos, const int* __restrict__ snd,
                          const int* __restrict__ rcv, int E) {
    int e = blockIdx.x * blockDim.x + threadIdx.x;
    if (e >= E) return;
    if (!g_live[e]) return;
    int s = __ldg(snd + e), r = __ldg(rcv + e);
    float d, ux, uy, uz;
    edge_geom(pos, s, r, d, ux, uy, uz);
    int slot = atomicAdd(&g_cursor[r], 1);
    float Y[16]; make_sh(ux, uy, uz, Y);
    float B[8];  make_basis(d, B);
    g_sender[slot] = s;
    float4* o4 = (float4*)(g_sh + (size_t)slot * 16);
    o4[0] = make_float4(Y[0], Y[1], Y[2], Y[3]);
    o4[1] = make_float4(Y[4], Y[5], Y[6], Y[7]);
    o4[2] = make_float4(Y[8], Y[9], Y[10], Y[11]);
    o4[3] = make_float4(Y[12], Y[13], Y[14], Y[15]);
    float4* b4 = (float4*)(g_basis + (size_t)slot * 8);
    b4[0] = make_float4(B[0], B[1], B[2], B[3]);
    b4[1] = make_float4(B[4], B[5], B[6], B[7]);
}

// ============================================================================
// Kernel 4 (phase A): feats (first MP) + CG self-interaction + embedding mul
// One warp per atom. Lane owns channels k0=lane, k1=lane+32.
// ============================================================================
__global__ __launch_bounds__(256) void k_phaseA(const int* __restrict__ species,
                                                const float* __restrict__ emb,
                                                int natoms) {
    __shared__ float sF[8][1024];
    int w = threadIdx.x >> 5, lane = threadIdx.x & 31;
    int a = blockIdx.x * 8 + w;
    if (a >= natoms) return;
    int c0 = lane & 15, n0 = lane >> 4, n1 = n0 + 2;

    float fa0[16], fa1[16];
    #pragma unroll
    for (int o = 0; o < 16; o++) { fa0[o] = 0.0f; fa1[o] = 0.0f; }

    int beg = __ldg(&g_offsets[a]), end = __ldg(&g_offsets[a + 1]);
    for (int e = beg; e < end; e++) {
        float sh[16];
        {
            const float4* p4 = (const float4*)(g_sh + (size_t)e * 16);
            float4 t;
            t = __ldg(p4 + 0); sh[0] = t.x; sh[1] = t.y; sh[2] = t.z; sh[3] = t.w;
            t = __ldg(p4 + 1); sh[4] = t.x; sh[5] = t.y; sh[6] = t.z; sh[7] = t.w;
            t = __ldg(p4 + 2); sh[8] = t.x; sh[9] = t.y; sh[10] = t.z; sh[11] = t.w;
            t = __ldg(p4 + 3); sh[12] = t.x; sh[13] = t.y; sh[14] = t.z; sh[15] = t.w;
        }
        float B[8];
        {
            const float4* p4 = (const float4*)(g_basis + (size_t)e * 8);
            float4 t;
            t = __ldg(p4 + 0); B[0] = t.x; B[1] = t.y; B[2] = t.z; B[3] = t.w;
            t = __ldg(p4 + 1); B[4] = t.x; B[5] = t.y; B[6] = t.z; B[7] = t.w;
        }
        int s = __ldg(&g_sender[e]);
        float ev = __ldg(emb + __ldg(species + s) * 16 + c0);
        float r0[4], r1[4];
        #pragma unroll
        for (int l = 0; l < 4; l++) {
            float a0 = 0.0f, a1 = 0.0f;
            #pragma unroll
            for (int b = 0; b < 8; b++) {
                a0 += B[b] * cWinv[l * 32 + b * 4 + n0];
                a1 += B[b] * cWinv[l * 32 + b * 4 + n1];
            }
            r0[l] = a0 * ev; r1[l] = a1 * ev;
        }
        #pragma unroll
        for (int o = 0; o < 16; o++) {
            fa0[o] += sh[o] * r0[lof(o)];
            fa1[o] += sh[o] * r1[lof(o)];
        }
    }
    #pragma unroll
    for (int o = 0; o < 16; o++) { fa0[o] *= 0.5f; fa1[o] *= 0.5f; }

    // stage feats to shared for dynamic-index bilinear self-interaction
    float* S = sF[w];
    #pragma unroll
    for (int o = 0; o < 16; o++) {
        S[o * 64 + lane] = fa0[o];
        S[o * 64 + 32 + lane] = fa1[o];
    }
    __syncwarp();

    float embA = __ldg(emb + __ldg(species + a) * 16 + c0);
    float* out = g_embedded + (size_t)a * 1024;
    #pragma unroll
    for (int o = 0; o < 16; o++) {
        float v0 = fa0[o], v1 = fa1[o];
        int b0 = cCsStart[o], b1 = cCsStart[o + 1];
        for (int t = b0; t < b1; t++) {
            int i = cCsI[t], j = cCsJ[t];
            float cv = cCsV[t];
            v0 += cv * S[i * 64 + lane] * S[j * 64 + lane];
            v1 += cv * S[i * 64 + 32 + lane] * S[j * 64 + 32 + lane];
        }
        out[o * 64 + lane] = v0 * embA;
        out[o * 64 + 32 + lane] = v1 * embA;
    }
}

// ============================================================================
// Kernel 5 (phase B): second MP (per-edge T matrix * gathered features * R_eq)
// + invariant contraction. One warp per atom.
// ============================================================================
__global__ __launch_bounds__(256) void k_phaseB(const float* __restrict__ Weq,
                                                int natoms) {
    __shared__ float sWeq[2048];
    __shared__ __align__(16) float sScr[8][1024];
    for (int i = threadIdx.x; i < 2048; i += 256) sWeq[i] = __ldg(Weq + i);
    __syncthreads();

    int w = threadIdx.x >> 5, lane = threadIdx.x & 31;
    int a = blockIdx.x * 8 + w;
    if (a >= natoms) return;
    float* Tw = sScr[w];

    float m0[16], m1[16];
    #pragma unroll
    for (int o = 0; o < 16; o++) { m0[o] = 0.0f; m1[o] = 0.0f; }

    int beg = __ldg(&g_offsets[a]), end = __ldg(&g_offsets[a + 1]);
    for (int e = beg; e < end; e++) {
        int s = __ldg(&g_sender[e]);
        float B[8];
        {
            const float4* p4 = (const float4*)(g_basis + (size_t)e * 8);
            float4 t;
            t = __ldg(p4 + 0); B[0] = t.x; B[1] = t.y; B[2] = t.z; B[3] = t.w;
            t = __ldg(p4 + 1); B[4] = t.x; B[5] = t.y; B[6] = t.z; B[7] = t.w;
        }
        // R_eq for this lane's two channels, all four L
        float q0[4], q1[4];
        #pragma unroll
        for (int L = 0; L < 4; L++) {
            float a0 = 0.0f, a1 = 0.0f;
            #pragma unroll
            for (int b = 0; b < 8; b++) {
                a0 += B[b] * sWeq[L * 512 + b * 64 + lane];
                a1 += B[b] * sWeq[L * 512 + b * 64 + 32 + lane];
            }
            q0[L] = a0; q1[L] = a1;
        }
        // assemble T[o][si] = sum_{l1,a} sh[sa] * CG   (lane-parallel over pairs)
        const float* shp = g_sh + (size_t)e * 16;
        for (int p = lane; p < 256; p += 32) {
            int t0 = dTpStart[p], t1 = dTpStart[p + 1];
            float v = 0.0f;
            for (int t = t0; t < t1; t++)
                v += dCtV[t] * __ldg(shp + dCtA[t]);
            Tw[p] = v;
        }
        // gather neighbor embedded features
        float x0[16], x1[16];
        const float* X = g_embedded + (size_t)s * 1024;
        #pragma unroll
        for (int si = 0; si < 16; si++) {
            x0[si] = __ldg(X + si * 64 + lane);
            x1[si] = __ldg(X + si * 64 + 32 + lane);
        }
        __syncwarp();
        const float4* T4 = (const float4*)Tw;
        #pragma unroll
        for (int o = 0; o < 16; o++) {
            float u0 = 0.0f, u1 = 0.0f;
            #pragma unroll
            for (int t = 0; t < 4; t++) {
                float4 tv = T4[o * 4 + t];
                u0 += tv.x * x0[t * 4 + 0] + tv.y * x0[t * 4 + 1]
                    + tv.z * x0[t * 4 + 2] + tv.w * x0[t * 4 + 3];
                u1 += tv.x * x1[t * 4 + 0] + tv.y * x1[t * 4 + 1]
                    + tv.z * x1[t * 4 + 2] + tv.w * x1[t * 4 + 3];
            }
            m0[o] += q0[lof(o)] * u0;
            m1[o] += q1[lof(o)] * u1;
        }
        __syncwarp();
    }

    // mp = 0.5 * acc ; stage for invariant contraction
    #pragma unroll
    for (int o = 0; o < 16; o++) {
        Tw[o * 64 + lane] = 0.5f * m0[o];
        Tw[o * 64 + 32 + lane] = 0.5f * m1[o];
    }
    __syncwarp();
    float v0 = Tw[lane], v1 = Tw[32 + lane];   // mp[0][0,:]
    int gn = cGn;
    for (int t = 0; t < gn; t++) {
        int gi = cGi[t], gj = cGj[t];
        float gv = cGv[t];
        v0 += gv * Tw[gi * 64 + lane] * Tw[gj * 64 + lane];
        v1 += gv * Tw[gi * 64 + 32 + lane] * Tw[gj * 64 + 32 + lane];
    }
    g_inv[(size_t)a * 64 + lane] = v0;
    g_inv[(size_t)a * 64 + 32 + lane] = v1;
}

// ============================================================================
// Kernel 6: MLP (silu -> silu -> dot w_last) per atom, one warp per atom
// ============================================================================
__global__ __launch_bounds__(256) void k_mlp(const float* __restrict__ W1,
                                             const float* __restrict__ W2,
                                             const float* __restrict__ wl,
                                             int natoms) {
    __shared__ float sW1[4096], sW2[4096], sWl[64];
    for (int i = threadIdx.x; i < 4096; i += 256) {
        sW1[i] = __ldg(W1 + i);
        sW2[i] = __ldg(W2 + i);
    }
    if (threadIdx.x < 64) sWl[threadIdx.x] = __ldg(wl + threadIdx.x);
    __syncthreads();

    int w = threadIdx.x >> 5, lane = threadIdx.x & 31;
    int a = blockIdx.x * 8 + w;
    if (a >= natoms) return;

    float i0 = g_inv[(size_t)a * 64 + lane];
    float i1 = g_inv[(size_t)a * 64 + 32 + lane];
    float h0 = 0.0f, h1 = 0.0f;
    #pragma unroll
    for (int j = 0; j < 64; j++) {
        float bj = __shfl_sync(0xffffffffu, (j < 32) ? i0 : i1, j & 31);
        h0 += bj * sW1[j * 64 + lane];
        h1 += bj * sW1[j * 64 + 32 + lane];
    }
    h0 = h0 / (1.0f + expf(-h0));
    h1 = h1 / (1.0f + expf(-h1));
    float g0 = 0.0f, g1 = 0.0f;
    #pragma unroll
    for (int j = 0; j < 64; j++) {
        float bj = __shfl_sync(0xffffffffu, (j < 32) ? h0 : h1, j & 31);
        g0 += bj * sW2[j * 64 + lane];
        g1 += bj * sW2[j * 64 + 32 + lane];
    }
    g0 = g0 / (1.0f + expf(-g0));
    g1 = g1 / (1.0f + expf(-g1));
    float p = g0 * sWl[lane] + g1 * sWl[32 + lane];
    #pragma unroll
    for (int off = 16; off; off >>= 1) p += __shfl_xor_sync(0xffffffffu, p, off);
    if (lane == 0) g_atomE[a] = p;
}

// ============================================================================
// Kernel 7: reduce atom energies (double accumulation)
// ============================================================================
__global__ void k_reduce(float* __restrict__ out, int n) {
    __shared__ double sred[1024];
    double s = 0.0;
    for (int i = threadIdx.x; i < n; i += 1024) s += (double)g_atomE[i];
    sred[threadIdx.x] = s;
    __syncthreads();
    for (int st = 512; st; st >>= 1) {
        if (threadIdx.x < st) sred[threadIdx.x] += sred[threadIdx.x + st];
        __syncthreads();
    }
    if (threadIdx.x == 0) out[0] = (float)sred[0];
}

// ============================================================================
// Host: exact port of the reference Clebsch-Gordan / real-SH coupling tables
// ============================================================================
namespace phace_host {

using cd = std::complex<double>;

static double hfact(int n) { double r = 1; for (int i = 2; i <= n; i++) r *= i; return r; }

static double hcg(int j1, int m1, int j2, int m2, int J, int M) {
    if (m1 + m2 != M || J < std::abs(j1 - j2) || J > j1 + j2) return 0.0;
    double pref = std::sqrt((2 * J + 1) * hfact(J + j1 - j2) * hfact(J - j1 + j2) *
                            hfact(j1 + j2 - J) / hfact(j1 + j2 + J + 1));
    pref *= std::sqrt(hfact(J + M) * hfact(J - M) * hfact(j1 - m1) * hfact(j1 + m1) *
                      hfact(j2 - m2) * hfact(j2 + m2));
    double s = 0.0;
    for (int k = 0; k <= j1 + j2 - J; k++) {
        int d0 = k, d1 = j1 + j2 - J - k, d2 = j1 - m1 - k, d3 = j2 + m2 - k;
        int d4 = J - j2 + m1 + k, d5 = J - j1 - m2 + k;
        if (d0 < 0 || d1 < 0 || d2 < 0 || d3 < 0 || d4 < 0 || d5 < 0) continue;
        double den = hfact(d0) * hfact(d1) * hfact(d2) * hfact(d3) * hfact(d4) * hfact(d5);
        s += ((k & 1) ? -1.0 : 1.0) / den;
    }
    return pref * s;
}

static void hureal(int l, cd U[7][7]) {
    for (int i = 0; i < 7; i++)
        for (int j = 0; j < 7; j++) U[i][j] = cd(0.0, 0.0);
    U[l][l] = cd(1.0, 0.0);
    const double is2 = 1.0 / std::sqrt(2.0);
    for (int m = 1; m <= l; m++) {
        double sg = (m & 1) ? -1.0 : 1.0;
        U[l + m][l + m] = cd(sg * is2, 0.0);
        U[l + m][l - m] = cd(is2, 0.0);
        U[l - m][l - m] = cd(0.0, is2);
        U[l - m][l + m] = cd(0.0, -is2 * sg);
    }
}

static void hrealcg(int l1, int l2, int L, float out[7][7][7]) {
    cd U1[7][7], U2[7][7], U3[7][7];
    hureal(l1, U1); hureal(l2, U2); hureal(L, U3);
    int d1 = 2 * l1 + 1, d2 = 2 * l2 + 1, d3 = 2 * L + 1;
    static cd T[7][7][7];
    double sre = 0.0, sim = 0.0;
    for (int a = 0; a < d1; a++)
        for (int b = 0; b < d2; b++)
            for (int c = 0; c < d3; c++) {
                cd acc(0.0, 0.0);
                for (int m = 0; m < d1; m++) {
                    cd u1 = U1[a][m];
                    if (u1.real() == 0.0 && u1.imag() == 0.0) continue;
                    for (int n = 0; n < d2; n++) {
                        cd u2 = U2[b][n];
                        if (u2.real() == 0.0 && u2.imag() == 0.0) continue;
                        for (int o = 0; o < d3; o++) {
                            cd u3 = std::conj(U3[c][o]);
                            if (u3.real() == 0.0 && u3.imag() == 0.0) continue;
                            double cgv = hcg(l1, m - l1, l2, n - l2, L, o - L);
                            if (cgv != 0.0) acc += u1 * u2 * u3 * cgv;
                        }
                    }
                }
                T[a][b][c] = acc;
                sre += std::abs(acc.real());
                sim += std::abs(acc.imag());
            }
    bool usere = (sre >= sim);
    for (int a = 0; a < d1; a++)
        for (int b = 0; b < d2; b++)
            for (int c = 0; c < d3; c++)
                out[a][b][c] = (float)(usere ? T[a][b][c].real() : T[a][b][c].imag());
}

struct HostTables {
    int cs_start[17]; short cs_i[MAXNZ]; short cs_j[MAXNZ]; float cs_v[MAXNZ]; int ncs;
    int tp_start[257]; short ct_a[MAXNZ]; float ct_v[MAXNZ]; int nct;
    short g_i[MAXG]; short g_j[MAXG]; float g_v[MAXG]; int ng;
};

static void build_tables(HostTables& H) {
    const int OFF[4] = {0, 1, 4, 9};
    struct E3 { short i, j; float v; };
    struct E2 { short a; float v; };
    std::vector<E3> so[16];
    std::vector<E2> tp[256];
    H.ng = 0;
    static float C[7][7][7];
    for (int l1 = 0; l1 < 4; l1++)
        for (int l2 = 0; l2 < 4; l2++) {
            int Llo = std::abs(l1 - l2), Lhi = std::min(l1 + l2, 3);
            for (int L = Llo; L <= Lhi; L++) {
                hrealcg(l1, l2, L, C);
                for (int a = 0; a < 2 * l1 + 1; a++)
                    for (int b = 0; b < 2 * l2 + 1; b++)
                        for (int c = 0; c < 2 * L + 1; c++) {
                            float v = C[a][b][c];
                            if (std::fabs(v) < 1e-7f) continue;
                            int o = OFF[L] + c, si = OFF[l2] + b, sa = OFF[l1] + a;
                            so[o].push_back({(short)sa, (short)si, v});
                            tp[o * 16 + si].push_back({(short)sa, v});
                            if (L == 0 && l1 == l2 && H.ng < MAXG) {
                                H.g_i[H.ng] = (short)sa;
                                H.g_j[H.ng] = (short)si;
                                H.g_v[H.ng] = v;
                                H.ng++;
                            }
                        }
            }
        }
    int idx = 0;
    for (int o = 0; o < 16; o++) {
        H.cs_start[o] = idx;
        for (auto& e : so[o]) {
            if (idx >= MAXNZ) break;
            H.cs_i[idx] = e.i; H.cs_j[idx] = e.j; H.cs_v[idx] = e.v; idx++;
        }
    }
    H.cs_start[16] = idx; H.ncs = idx;
    idx = 0;
    for (int p = 0; p < 256; p++) {
        H.tp_start[p] = idx;
        for (auto& e : tp[p]) {
            if (idx >= MAXNZ) break;
            H.ct_a[idx] = e.a; H.ct_v[idx] = e.v; idx++;
        }
    }
    H.tp_start[256] = idx; H.nct = idx;
}

} // namespace phace_host

// ============================================================================
// kernel_launch
// ============================================================================
extern "C" void kernel_launch(void* const* d_in, const int* in_sizes, int n_in,
                              void* d_out, int out_size) {
    const float* pos     = (const float*)d_in[0];
    const float* emb     = (const float*)d_in[1];
    const float* Winv    = (const float*)d_in[2];
    const float* Weq     = (const float*)d_in[3];
    const float* W1      = (const float*)d_in[4];
    const float* W2      = (const float*)d_in[5];
    const float* wl      = (const float*)d_in[6];
    const int*   species = (const int*)d_in[7];
    const int*   snd     = (const int*)d_in[8];
    const int*   rcv     = (const int*)d_in[9];
    int N = in_sizes[7];
    int E = in_sizes[8];
    if (N > MAXN_AT) N = MAXN_AT;
    if (E > MAXE_ED) E = MAXE_ED;

    static phace_host::HostTables H;   // static: source must persist for graph replays
    phace_host::build_tables(H);       // deterministic, rebuilt every call

    cudaMemcpyToSymbolAsync(cCsStart, H.cs_start, sizeof(int) * 17, 0, cudaMemcpyHostToDevice, 0);
    cudaMemcpyToSymbolAsync(cCsI, H.cs_i, sizeof(short) * H.ncs, 0, cudaMemcpyHostToDevice, 0);
    cudaMemcpyToSymbolAsync(cCsJ, H.cs_j, sizeof(short) * H.ncs, 0, cudaMemcpyHostToDevice, 0);
    cudaMemcpyToSymbolAsync(cCsV, H.cs_v, sizeof(float) * H.ncs, 0, cudaMemcpyHostToDevice, 0);
    cudaMemcpyToSymbolAsync(dTpStart, H.tp_start, sizeof(int) * 257, 0, cudaMemcpyHostToDevice, 0);
    cudaMemcpyToSymbolAsync(dCtA, H.ct_a, sizeof(short) * H.nct, 0, cudaMemcpyHostToDevice, 0);
    cudaMemcpyToSymbolAsync(dCtV, H.ct_v, sizeof(float) * H.nct, 0, cudaMemcpyHostToDevice, 0);
    cudaMemcpyToSymbolAsync(cGn, &H.ng, sizeof(int), 0, cudaMemcpyHostToDevice, 0);
    cudaMemcpyToSymbolAsync(cGi, H.g_i, sizeof(short) * (H.ng > 0 ? H.ng : 1), 0, cudaMemcpyHostToDevice, 0);
    cudaMemcpyToSymbolAsync(cGj, H.g_j, sizeof(short) * (H.ng > 0 ? H.ng : 1), 0, cudaMemcpyHostToDevice, 0);
    cudaMemcpyToSymbolAsync(cGv, H.g_v, sizeof(float) * (H.ng > 0 ? H.ng : 1), 0, cudaMemcpyHostToDevice, 0);
    cudaMemcpyToSymbolAsync(cWinv, Winv, 128 * sizeof(float), 0, cudaMemcpyDeviceToDevice, 0);

    k_zero<<<(N + 255) / 256, 256>>>(N);
    k_count<<<(E + 255) / 256, 256>>>(pos, snd, rcv, E);
    k_scan<<<1, 1024>>>(N);
    k_scatter<<<(E + 255) / 256, 256>>>(pos, snd, rcv, E);
    int ab = (N + 7) / 8;
    k_phaseA<<<ab, 256>>>(species, emb, N);
    k_phaseB<<<ab, 256>>>(Weq, N);
    k_mlp<<<ab, 256>>>(W1, W2, wl, N);
    k_reduce<<<1, 1024>>>((float*)d_out, N);
}

// round 5
// speedup vs baseline: 1.6901x; 1.6901x over previous
#include <cuda_runtime.h>
#include <cuda_bf16.h>
#include <cmath>
#include <cstdint>
#include <cstring>
#include <complex>
#include <vector>
#include <algorithm>

// ============================================================================
// Sizes
// ============================================================================
#define MAXN_AT 16384
#define MAXE_ED 262144
#define MAXNZ   2048
#define MAXG    96

// ============================================================================
// Device scratch (static; no allocations allowed)
// ============================================================================
__device__ __align__(16) float  g_sh[(size_t)MAXE_ED * 16];
__device__ __align__(16) float  g_basis[(size_t)MAXE_ED * 8];
__device__ int    g_sender[MAXE_ED];
__device__ unsigned char g_live[MAXE_ED];
__device__ int    g_count[MAXN_AT];
__device__ int    g_cursor[MAXN_AT];
__device__ int    g_offsets[MAXN_AT + 1];
__device__ __align__(16) float  g_embedded[(size_t)MAXN_AT * 1024];
__device__ float  g_embAt[(size_t)MAXN_AT * 16];
__device__ float  g_inv[(size_t)MAXN_AT * 64];
__device__ float  g_atomE[MAXN_AT];
__device__ float  g_Winv[128];

// Packed sparse tables (one LDG.64 per nonzero)
__constant__ int  cCsStart[17];
__device__ int2   dSelf[MAXNZ];     // {(i*64)|(j*64<<16), bitcast(v)}
__device__ int2   dTstart[256];     // per p={o*16+si}: {start, end}
__device__ int2   dTent[MAXNZ];     // {a, bitcast(v)}
__device__ int2   dG[MAXG];         // {(i*32)|(j*32<<16), bitcast(v)}

// slot -> l map (compile-time foldable)
__host__ __device__ __forceinline__ constexpr int lof(int s) {
    return s == 0 ? 0 : (s < 4 ? 1 : (s < 9 ? 2 : 3));
}

// ============================================================================
// Edge geometry
// ============================================================================
__device__ __forceinline__ void edge_geom(const float* pos, int s, int r,
                                          float& d, float& ux, float& uy, float& uz) {
    float dx = __ldg(pos + 3 * r + 0) - __ldg(pos + 3 * s + 0);
    float dy = __ldg(pos + 3 * r + 1) - __ldg(pos + 3 * s + 1);
    float dz = __ldg(pos + 3 * r + 2) - __ldg(pos + 3 * s + 2);
    d = sqrtf(dx * dx + dy * dy + dz * dz + 1e-12f);
    ux = dx / d; uy = dy / d; uz = dz / d;
}

__device__ __forceinline__ void make_sh(float x, float y, float z, float* Y) {
    Y[0] = 0.28209479177387814f;
    const float c1 = 0.4886025119029199f;
    Y[1] = c1 * y; Y[2] = c1 * z; Y[3] = c1 * x;
    Y[4] = 1.0925484305920792f * x * y;
    Y[5] = 1.0925484305920792f * y * z;
    Y[6] = 0.31539156525252005f * (3.0f * z * z - 1.0f);
    Y[7] = 1.0925484305920792f * x * z;
    Y[8] = 0.5462742152960396f * (x * x - y * y);
    Y[9]  = 0.5900435899266435f * y * (3.0f * x * x - y * y);
    Y[10] = 2.890611442640554f * x * y * z;
    Y[11] = 0.4570457994644658f * y * (5.0f * z * z - 1.0f);
    Y[12] = 0.3731763325901154f * z * (5.0f * z * z - 3.0f);
    Y[13] = 0.4570457994644658f * x * (5.0f * z * z - 1.0f);
    Y[14] = 1.445305721320277f * z * (x * x - y * y);
    Y[15] = 0.5900435899266435f * x * (x * x - 3.0f * y * y);
}

__device__ __forceinline__ void make_basis(float d, float* B) {
    float fc = 0.5f * (cosf(3.14159274101257324f * d / 5.0f) + 1.0f);
    #pragma unroll
    for (int i = 0; i < 8; i++) {
        float mu = (float)(5.0 * (double)i / 7.0);
        float t = (d - mu) / 0.625f;
        B[i] = expf(-0.5f * t * t) * fc;
    }
}

// ============================================================================
// Kernel: zero counts + expand species embeddings per atom
// ============================================================================
__global__ void k_prep(const int* __restrict__ species, const float* __restrict__ emb,
                       int n) {
    int i = blockIdx.x * blockDim.x + threadIdx.x;
    if (i >= n) return;
    g_count[i] = 0;
    int sp = __ldg(species + i);
    #pragma unroll
    for (int c = 0; c < 16; c++)
        g_embAt[i * 16 + c] = __ldg(emb + sp * 16 + c);
}

// ============================================================================
// Kernel: count live edges per receiver
// ============================================================================
__global__ void k_count(const float* __restrict__ pos, const int* __restrict__ snd,
                        const int* __restrict__ rcv, int E) {
    int e = blockIdx.x * blockDim.x + threadIdx.x;
    if (e >= E) return;
    int s = __ldg(snd + e), r = __ldg(rcv + e);
    float d, ux, uy, uz;
    edge_geom(pos, s, r, d, ux, uy, uz);
    unsigned char live = (d < 5.0f) ? 1 : 0;
    g_live[e] = live;
    if (live) atomicAdd(&g_count[r], 1);
}

// ============================================================================
// Kernel: exclusive scan (single block)
// ============================================================================
__global__ void k_scan(int n) {
    __shared__ int part[1024];
    int tid = threadIdx.x;
    int chunk = (n + 1023) >> 10;
    int beg = tid * chunk, end = min(beg + chunk, n);
    int s = 0;
    for (int i = beg; i < end; i++) s += g_count[i];
    part[tid] = s;
    __syncthreads();
    for (int off = 1; off < 1024; off <<= 1) {
        int v = (tid >= off) ? part[tid - off] : 0;
        __syncthreads();
        part[tid] += v;
        __syncthreads();
    }
    int run = (tid == 0) ? 0 : part[tid - 1];
    for (int i = beg; i < end; i++) {
        g_offsets[i] = run;
        g_cursor[i] = run;
        run += g_count[i];
    }
    if (tid == 1023) g_offsets[n] = part[1023];
}

// ============================================================================
// Kernel: scatter live edges receiver-sorted
// ============================================================================
__global__ void k_scatter(const float* __restrict__ pos, const int* __restrict__ snd,
                          const int* __restrict__ rcv, int E) {
    int e = blockIdx.x * blockDim.x + threadIdx.x;
    if (e >= E) return;
    if (!g_live[e]) return;
    int s = __ldg(snd + e), r = __ldg(rcv + e);
    float d, ux, uy, uz;
    edge_geom(pos, s, r, d, ux, uy, uz);
    int slot = atomicAdd(&g_cursor[r], 1);
    float Y[16]; make_sh(ux, uy, uz, Y);
    float B[8];  make_basis(d, B);
    g_sender[slot] = s;
    float4* o4 = (float4*)(g_sh + (size_t)slot * 16);
    o4[0] = make_float4(Y[0], Y[1], Y[2], Y[3]);
    o4[1] = make_float4(Y[4], Y[5], Y[6], Y[7]);
    o4[2] = make_float4(Y[8], Y[9], Y[10], Y[11]);
    o4[3] = make_float4(Y[12], Y[13], Y[14], Y[15]);
    float4* b4 = (float4*)(g_basis + (size_t)slot * 8);
    b4[0] = make_float4(B[0], B[1], B[2], B[3]);
    b4[1] = make_float4(B[4], B[5], B[6], B[7]);
}

// ============================================================================
// Phase A: first MP + CG self-interaction + embedding mul.
// One warp per atom; block = 128 (4 atoms). Lane owns k0=lane, k1=lane+32.
// ============================================================================
__global__ __launch_bounds__(128) void k_phaseA(int natoms) {
    __shared__ float sWinv[128];
    __shared__ float sF[4][1024];
    for (int i = threadIdx.x; i < 128; i += 128) sWinv[i] = g_Winv[i];
    __syncthreads();

    int w = threadIdx.x >> 5, lane = threadIdx.x & 31;
    int a = blockIdx.x * 4 + w;
    if (a >= natoms) return;
    int c0 = lane & 15, n0 = lane >> 4, n1 = n0 + 2;

    float fa0[16], fa1[16];
    #pragma unroll
    for (int o = 0; o < 16; o++) { fa0[o] = 0.0f; fa1[o] = 0.0f; }

    int beg = __ldg(&g_offsets[a]), end = __ldg(&g_offsets[a + 1]);
    for (int e = beg; e < end; e++) {
        float sh[16];
        {
            const float4* p4 = (const float4*)(g_sh + (size_t)e * 16);
            float4 t;
            t = __ldg(p4 + 0); sh[0] = t.x; sh[1] = t.y; sh[2] = t.z; sh[3] = t.w;
            t = __ldg(p4 + 1); sh[4] = t.x; sh[5] = t.y; sh[6] = t.z; sh[7] = t.w;
            t = __ldg(p4 + 2); sh[8] = t.x; sh[9] = t.y; sh[10] = t.z; sh[11] = t.w;
            t = __ldg(p4 + 3); sh[12] = t.x; sh[13] = t.y; sh[14] = t.z; sh[15] = t.w;
        }
        float B[8];
        {
            const float4* p4 = (const float4*)(g_basis + (size_t)e * 8);
            float4 t;
            t = __ldg(p4 + 0); B[0] = t.x; B[1] = t.y; B[2] = t.z; B[3] = t.w;
            t = __ldg(p4 + 1); B[4] = t.x; B[5] = t.y; B[6] = t.z; B[7] = t.w;
        }
        int s = __ldg(&g_sender[e]);
        float ev = __ldg(&g_embAt[s * 16 + c0]);
        float r0[4], r1[4];
        #pragma unroll
        for (int l = 0; l < 4; l++) {
            float a0 = 0.0f, a1 = 0.0f;
            #pragma unroll
            for (int b = 0; b < 8; b++) {
                a0 += B[b] * sWinv[l * 32 + b * 4 + n0];
                a1 += B[b] * sWinv[l * 32 + b * 4 + n1];
            }
            r0[l] = a0 * ev; r1[l] = a1 * ev;
        }
        #pragma unroll
        for (int o = 0; o < 16; o++) {
            fa0[o] += sh[o] * r0[lof(o)];
            fa1[o] += sh[o] * r1[lof(o)];
        }
    }
    #pragma unroll
    for (int o = 0; o < 16; o++) { fa0[o] *= 0.5f; fa1[o] *= 0.5f; }

    // stage feats for dynamic-index bilinear self-interaction
    float* S = sF[w];
    #pragma unroll
    for (int o = 0; o < 16; o++) {
        S[o * 64 + lane] = fa0[o];
        S[o * 64 + 32 + lane] = fa1[o];
    }
    __syncwarp();

    float embA = __ldg(&g_embAt[a * 16 + c0]);
    float* out = g_embedded + (size_t)a * 1024;
    #pragma unroll
    for (int o = 0; o < 16; o++) {
        float v0 = fa0[o], v1 = fa1[o];
        int b0 = cCsStart[o], b1 = cCsStart[o + 1];
        for (int t = b0; t < b1; t++) {
            int2 en = __ldg(&dSelf[t]);
            int i64 = en.x & 0xFFFF, j64 = (en.x >> 16) & 0xFFFF;
            float cv = __int_as_float(en.y);
            v0 += cv * S[i64 + lane] * S[j64 + lane];
            v1 += cv * S[i64 + 32 + lane] * S[j64 + 32 + lane];
        }
        out[o * 64 + lane] = v0 * embA;
        out[o * 64 + 32 + lane] = v1 * embA;
    }
}

// ============================================================================
// Phase B: second MP + invariant contraction.
// TWO warps per atom (each owns 32 channels). Block = 128 = 2 atoms.
// ============================================================================
__global__ __launch_bounds__(128) void k_phaseB(const float* __restrict__ Weq,
                                                int natoms, int nG) {
    __shared__ float sWeq[2048];
    __shared__ __align__(16) float sT[4][512];   // per warp: T (256) then mp-stage (512)
    __shared__ float sSh[4][16];
    for (int i = threadIdx.x; i < 2048; i += 128) sWeq[i] = __ldg(Weq + i);
    __syncthreads();

    int wib = threadIdx.x >> 5;                  // warp in block 0..3
    int lane = threadIdx.x & 31;
    int a = blockIdx.x * 2 + (wib >> 1);
    if (a >= natoms) return;
    int k = ((wib & 1) << 5) + lane;             // this warp's channel
    float* Tw = sT[wib];
    float* Sh = sSh[wib];

    float m[16];
    #pragma unroll
    for (int o = 0; o < 16; o++) m[o] = 0.0f;

    int beg = __ldg(&g_offsets[a]), end = __ldg(&g_offsets[a + 1]);
    for (int e = beg; e < end; e++) {
        int s = __ldg(&g_sender[e]);
        // stage sh for this edge (per-warp copy)
        if (lane < 16) Sh[lane] = __ldg(g_sh + (size_t)e * 16 + lane);
        float B[8];
        {
            const float4* p4 = (const float4*)(g_basis + (size_t)e * 8);
            float4 t;
            t = __ldg(p4 + 0); B[0] = t.x; B[1] = t.y; B[2] = t.z; B[3] = t.w;
            t = __ldg(p4 + 1); B[4] = t.x; B[5] = t.y; B[6] = t.z; B[7] = t.w;
        }
        // R_eq for this warp's channel, all four L
        float q[4];
        #pragma unroll
        for (int L = 0; L < 4; L++) {
            float acc = 0.0f;
            #pragma unroll
            for (int b = 0; b < 8; b++)
                acc += B[b] * sWeq[L * 512 + b * 64 + k];
            q[L] = acc;
        }
        __syncwarp();
        // assemble T[o*16+si] (each warp builds its own copy; packed tables)
        #pragma unroll
        for (int pi = 0; pi < 8; pi++) {
            int p = lane + pi * 32;
            int2 se = __ldg(&dTstart[p]);
            float v = 0.0f;
            for (int t = se.x; t < se.y; t++) {
                int2 en = __ldg(&dTent[t]);
                v += __int_as_float(en.y) * Sh[en.x];
            }
            Tw[p] = v;
        }
        // gather neighbor features for this warp's channel
        float x[16];
        const float* X = g_embedded + (size_t)s * 1024 + k;
        #pragma unroll
        for (int si = 0; si < 16; si++) x[si] = __ldg(X + si * 64);
        __syncwarp();
        const float4* T4 = (const float4*)Tw;
        #pragma unroll
        for (int o = 0; o < 16; o++) {
            float u = 0.0f;
            #pragma unroll
            for (int t = 0; t < 4; t++) {
                float4 tv = T4[o * 4 + t];
                u += tv.x * x[t * 4 + 0] + tv.y * x[t * 4 + 1]
                   + tv.z * x[t * 4 + 2] + tv.w * x[t * 4 + 3];
            }
            m[o] += q[lof(o)] * u;
        }
        __syncwarp();
    }

    // mp = 0.5*m ; stage for invariant contraction (dynamic pair indices)
    #pragma unroll
    for (int o = 0; o < 16; o++) Tw[o * 32 + lane] = 0.5f * m[o];
    __syncwarp();
    float inv = Tw[lane];                        // mp[0][0]
    for (int t = 0; t < nG; t++) {
        int2 en = __ldg(&dG[t]);
        int i32 = en.x & 0xFFFF, j32 = (en.x >> 16) & 0xFFFF;
        inv += __int_as_float(en.y) * Tw[i32 + lane] * Tw[j32 + lane];
    }
    g_inv[(size_t)a * 64 + k] = inv;
}

// ============================================================================
// MLP per atom (one warp per atom, block 128)
// ============================================================================
__global__ __launch_bounds__(128) void k_mlp(const float* __restrict__ W1,
                                             const float* __restrict__ W2,
                                             const float* __restrict__ wl,
                                             int natoms) {
    __shared__ float sW1[4096], sW2[4096], sWl[64];
    for (int i = threadIdx.x; i < 4096; i += 128) {
        sW1[i] = __ldg(W1 + i);
        sW2[i] = __ldg(W2 + i);
    }
    if (threadIdx.x < 64) sWl[threadIdx.x] = __ldg(wl + threadIdx.x);
    __syncthreads();

    int w = threadIdx.x >> 5, lane = threadIdx.x & 31;
    int a = blockIdx.x * 4 + w;
    if (a >= natoms) return;

    float i0 = g_inv[(size_t)a * 64 + lane];
    float i1 = g_inv[(size_t)a * 64 + 32 + lane];
    float h0 = 0.0f, h1 = 0.0f;
    #pragma unroll
    for (int j = 0; j < 64; j++) {
        float bj = __shfl_sync(0xffffffffu, (j < 32) ? i0 : i1, j & 31);
        h0 += bj * sW1[j * 64 + lane];
        h1 += bj * sW1[j * 64 + 32 + lane];
    }
    h0 = h0 / (1.0f + expf(-h0));
    h1 = h1 / (1.0f + expf(-h1));
    float g0 = 0.0f, g1 = 0.0f;
    #pragma unroll
    for (int j = 0; j < 64; j++) {
        float bj = __shfl_sync(0xffffffffu, (j < 32) ? h0 : h1, j & 31);
        g0 += bj * sW2[j * 64 + lane];
        g1 += bj * sW2[j * 64 + 32 + lane];
    }
    g0 = g0 / (1.0f + expf(-g0));
    g1 = g1 / (1.0f + expf(-g1));
    float p = g0 * sWl[lane] + g1 * sWl[32 + lane];
    #pragma unroll
    for (int off = 16; off; off >>= 1) p += __shfl_xor_sync(0xffffffffu, p, off);
    if (lane == 0) g_atomE[a] = p;
}

// ============================================================================
// Reduce atom energies (double accumulation)
// ============================================================================
__global__ void k_reduce(float* __restrict__ out, int n) {
    __shared__ double sred[1024];
    double s = 0.0;
    for (int i = threadIdx.x; i < n; i += 1024) s += (double)g_atomE[i];
    sred[threadIdx.x] = s;
    __syncthreads();
    for (int st = 512; st; st >>= 1) {
        if (threadIdx.x < st) sred[threadIdx.x] += sred[threadIdx.x + st];
        __syncthreads();
    }
    if (threadIdx.x == 0) out[0] = (float)sred[0];
}

// ============================================================================
// Host: exact port of the reference Clebsch-Gordan / real-SH coupling tables
// ============================================================================
namespace phace_host {

using cd = std::complex<double>;

static double hfact(int n) { double r = 1; for (int i = 2; i <= n; i++) r *= i; return r; }

static double hcg(int j1, int m1, int j2, int m2, int J, int M) {
    if (m1 + m2 != M || J < std::abs(j1 - j2) || J > j1 + j2) return 0.0;
    double pref = std::sqrt((2 * J + 1) * hfact(J + j1 - j2) * hfact(J - j1 + j2) *
                            hfact(j1 + j2 - J) / hfact(j1 + j2 + J + 1));
    pref *= std::sqrt(hfact(J + M) * hfact(J - M) * hfact(j1 - m1) * hfact(j1 + m1) *
                      hfact(j2 - m2) * hfact(j2 + m2));
    double s = 0.0;
    for (int k = 0; k <= j1 + j2 - J; k++) {
        int d0 = k, d1 = j1 + j2 - J - k, d2 = j1 - m1 - k, d3 = j2 + m2 - k;
        int d4 = J - j2 + m1 + k, d5 = J - j1 - m2 + k;
        if (d0 < 0 || d1 < 0 || d2 < 0 || d3 < 0 || d4 < 0 || d5 < 0) continue;
        double den = hfact(d0) * hfact(d1) * hfact(d2) * hfact(d3) * hfact(d4) * hfact(d5);
        s += ((k & 1) ? -1.0 : 1.0) / den;
    }
    return pref * s;
}

static void hureal(int l, cd U[7][7]) {
    for (int i = 0; i < 7; i++)
        for (int j = 0; j < 7; j++) U[i][j] = cd(0.0, 0.0);
    U[l][l] = cd(1.0, 0.0);
    const double is2 = 1.0 / std::sqrt(2.0);
    for (int m = 1; m <= l; m++) {
        double sg = (m & 1) ? -1.0 : 1.0;
        U[l + m][l + m] = cd(sg * is2, 0.0);
        U[l + m][l - m] = cd(is2, 0.0);
        U[l - m][l - m] = cd(0.0, is2);
        U[l - m][l + m] = cd(0.0, -is2 * sg);
    }
}

static void hrealcg(int l1, int l2, int L, float out[7][7][7]) {
    cd U1[7][7], U2[7][7], U3[7][7];
    hureal(l1, U1); hureal(l2, U2); hureal(L, U3);
    int d1 = 2 * l1 + 1, d2 = 2 * l2 + 1, d3 = 2 * L + 1;
    static cd T[7][7][7];
    double sre = 0.0, sim = 0.0;
    for (int a = 0; a < d1; a++)
        for (int b = 0; b < d2; b++)
            for (int c = 0; c < d3; c++) {
                cd acc(0.0, 0.0);
                for (int m = 0; m < d1; m++) {
                    cd u1 = U1[a][m];
                    if (u1.real() == 0.0 && u1.imag() == 0.0) continue;
                    for (int n = 0; n < d2; n++) {
                        cd u2 = U2[b][n];
                        if (u2.real() == 0.0 && u2.imag() == 0.0) continue;
                        for (int o = 0; o < d3; o++) {
                            cd u3 = std::conj(U3[c][o]);
                            if (u3.real() == 0.0 && u3.imag() == 0.0) continue;
                            double cgv = hcg(l1, m - l1, l2, n - l2, L, o - L);
                            if (cgv != 0.0) acc += u1 * u2 * u3 * cgv;
                        }
                    }
                }
                T[a][b][c] = acc;
                sre += std::abs(acc.real());
                sim += std::abs(acc.imag());
            }
    bool usere = (sre >= sim);
    for (int a = 0; a < d1; a++)
        for (int b = 0; b < d2; b++)
            for (int c = 0; c < d3; c++)
                out[a][b][c] = (float)(usere ? T[a][b][c].real() : T[a][b][c].imag());
}

static int f2i(float v) { int r; std::memcpy(&r, &v, 4); return r; }

struct HostTables {
    int  cs_start[17]; int2 self[MAXNZ]; int ncs;
    int2 tstart[256];  int2 tent[MAXNZ]; int nct;
    int2 g[MAXG];      int ng;
};

static void build_tables(HostTables& H) {
    const int OFF[4] = {0, 1, 4, 9};
    struct E3 { short i, j; float v; };
    struct E2 { short a; float v; };
    std::vector<E3> so[16];
    std::vector<E2> tp[256];
    H.ng = 0;
    static float C[7][7][7];
    for (int l1 = 0; l1 < 4; l1++)
        for (int l2 = 0; l2 < 4; l2++) {
            int Llo = std::abs(l1 - l2), Lhi = std::min(l1 + l2, 3);
            for (int L = Llo; L <= Lhi; L++) {
                hrealcg(l1, l2, L, C);
                for (int a = 0; a < 2 * l1 + 1; a++)
                    for (int b = 0; b < 2 * l2 + 1; b++)
                        for (int c = 0; c < 2 * L + 1; c++) {
                            float v = C[a][b][c];
                            if (std::fabs(v) < 1e-7f) continue;
                            int o = OFF[L] + c, si = OFF[l2] + b, sa = OFF[l1] + a;
                            so[o].push_back({(short)sa, (short)si, v});
                            tp[o * 16 + si].push_back({(short)sa, v});
                            if (L == 0 && l1 == l2 && H.ng < MAXG) {
                                H.g[H.ng].x = (sa * 32) | ((si * 32) << 16);
                                H.g[H.ng].y = f2i(v);
                                H.ng++;
                            }
                        }
            }
        }
    int idx = 0;
    for (int o = 0; o < 16; o++) {
        H.cs_start[o] = idx;
        for (auto& e : so[o]) {
            if (idx >= MAXNZ) break;
            H.self[idx].x = (e.i * 64) | ((e.j * 64) << 16);
            H.self[idx].y = f2i(e.v);
            idx++;
        }
    }
    H.cs_start[16] = idx; H.ncs = idx;
    idx = 0;
    for (int p = 0; p < 256; p++) {
        H.tstart[p].x = idx;
        for (auto& e : tp[p]) {
            if (idx >= MAXNZ) break;
            H.tent[idx].x = e.a;
            H.tent[idx].y = f2i(e.v);
            idx++;
        }
        H.tstart[p].y = idx;
    }
    H.nct = idx;
}

} // namespace phace_host

// ============================================================================
// kernel_launch
// ============================================================================
extern "C" void kernel_launch(void* const* d_in, const int* in_sizes, int n_in,
                              void* d_out, int out_size) {
    const float* pos     = (const float*)d_in[0];
    const float* emb     = (const float*)d_in[1];
    const float* Winv    = (const float*)d_in[2];
    const float* Weq     = (const float*)d_in[3];
    const float* W1      = (const float*)d_in[4];
    const float* W2      = (const float*)d_in[5];
    const float* wl      = (const float*)d_in[6];
    const int*   species = (const int*)d_in[7];
    const int*   snd     = (const int*)d_in[8];
    const int*   rcv     = (const int*)d_in[9];
    int N = in_sizes[7];
    int E = in_sizes[8];
    if (N > MAXN_AT) N = MAXN_AT;
    if (E > MAXE_ED) E = MAXE_ED;

    static phace_host::HostTables H;   // static: must persist for graph replays
    phace_host::build_tables(H);       // deterministic, rebuilt every call

    cudaMemcpyToSymbolAsync(cCsStart, H.cs_start, sizeof(int) * 17, 0, cudaMemcpyHostToDevice, 0);
    cudaMemcpyToSymbolAsync(dSelf, H.self, sizeof(int2) * H.ncs, 0, cudaMemcpyHostToDevice, 0);
    cudaMemcpyToSymbolAsync(dTstart, H.tstart, sizeof(int2) * 256, 0, cudaMemcpyHostToDevice, 0);
    cudaMemcpyToSymbolAsync(dTent, H.tent, sizeof(int2) * H.nct, 0, cudaMemcpyHostToDevice, 0);
    cudaMemcpyToSymbolAsync(dG, H.g, sizeof(int2) * (H.ng > 0 ? H.ng : 1), 0, cudaMemcpyHostToDevice, 0);
    cudaMemcpyToSymbolAsync(g_Winv, Winv, 128 * sizeof(float), 0, cudaMemcpyDeviceToDevice, 0);

    k_prep<<<(N + 127) / 128, 128>>>(species, emb, N);
    k_count<<<(E + 255) / 256, 256>>>(pos, snd, rcv, E);
    k_scan<<<1, 1024>>>(N);
    k_scatter<<<(E + 255) / 256, 256>>>(pos, snd, rcv, E);
    k_phaseA<<<(N + 3) / 4, 128>>>(N);
    k_phaseB<<<(N + 1) / 2, 128>>>(Weq, N, H.ng);
    k_mlp<<<(N + 3) / 4, 128>>>(W1, W2, wl, N);
    k_reduce<<<1, 1024>>>((float*)d_out, N);
}

// round 6
// speedup vs baseline: 1.7101x; 1.0118x over previous
#include <cuda_runtime.h>
#include <cuda_bf16.h>
#include <cmath>
#include <cstdint>
#include <cstring>
#include <complex>
#include <vector>
#include <algorithm>

typedef unsigned long long ull;

// ============================================================================
// Sizes
// ============================================================================
#define MAXN_AT 16384
#define MAXE_ED 262144
#define MAXNZ   512
#define MAXG    96

// ============================================================================
// Device scratch (static; no allocations allowed)
// ============================================================================
__device__ __align__(16) float  g_sh[(size_t)MAXE_ED * 16];
__device__ __align__(16) float  g_basis[(size_t)MAXE_ED * 8];
__device__ int    g_sender[MAXE_ED];
__device__ unsigned char g_live[MAXE_ED];
__device__ int    g_count[MAXN_AT];
__device__ int    g_cursor[MAXN_AT];
__device__ int    g_offsets[MAXN_AT + 1];
__device__ __align__(16) float  g_embedded[(size_t)MAXN_AT * 1024]; // [atom][k(64)][si(16)]
__device__ float  g_embAt[(size_t)MAXN_AT * 16];
__device__ float  g_inv[(size_t)MAXN_AT * 64];
__device__ float  g_atomE[MAXN_AT];
__device__ float  g_Winv[128];

// Sparse tables
__constant__ int  cCsStart[17];
__device__ __align__(16) ulonglong2 dSelf2[MAXNZ]; // {meta=(i*32)|(j*32<<16), cv duplicated f32x2}
__device__ int2   dTstart[256];                    // per p={o*16+si}: {start, end}
__device__ int2   dTent[MAXNZ];                    // {a, bitcast(v)}
__device__ int2   dG[MAXG];                        // {(i*32)|(j*32<<16), bitcast(v)}

// slot -> l map (compile-time foldable)
__host__ __device__ __forceinline__ constexpr int lof(int s) {
    return s == 0 ? 0 : (s < 4 ? 1 : (s < 9 ? 2 : 3));
}

// ============================================================================
// f32x2 helpers (Blackwell packed fp32)
// ============================================================================
__device__ __forceinline__ ull pk2(float lo, float hi) {
    ull r; asm("mov.b64 %0, {%1, %2};" : "=l"(r) : "f"(lo), "f"(hi)); return r;
}
__device__ __forceinline__ void upk2(ull v, float& lo, float& hi) {
    asm("mov.b64 {%0, %1}, %2;" : "=f"(lo), "=f"(hi) : "l"(v));
}
__device__ __forceinline__ ull fma2(ull a, ull b, ull c) {
    ull r; asm("fma.rn.f32x2 %0, %1, %2, %3;" : "=l"(r) : "l"(a), "l"(b), "l"(c)); return r;
}
__device__ __forceinline__ ull mul2(ull a, ull b) {
    ull r; asm("mul.rn.f32x2 %0, %1, %2;" : "=l"(r) : "l"(a), "l"(b)); return r;
}
#define HALF2 0x3F0000003F000000ULL

// ============================================================================
// Edge geometry
// ============================================================================
__device__ __forceinline__ void edge_geom(const float* pos, int s, int r,
                                          float& d, float& ux, float& uy, float& uz) {
    float dx = __ldg(pos + 3 * r + 0) - __ldg(pos + 3 * s + 0);
    float dy = __ldg(pos + 3 * r + 1) - __ldg(pos + 3 * s + 1);
    float dz = __ldg(pos + 3 * r + 2) - __ldg(pos + 3 * s + 2);
    d = sqrtf(dx * dx + dy * dy + dz * dz + 1e-12f);
    ux = dx / d; uy = dy / d; uz = dz / d;
}

__device__ __forceinline__ void make_sh(float x, float y, float z, float* Y) {
    Y[0] = 0.28209479177387814f;
    const float c1 = 0.4886025119029199f;
    Y[1] = c1 * y; Y[2] = c1 * z; Y[3] = c1 * x;
    Y[4] = 1.0925484305920792f * x * y;
    Y[5] = 1.0925484305920792f * y * z;
    Y[6] = 0.31539156525252005f * (3.0f * z * z - 1.0f);
    Y[7] = 1.0925484305920792f * x * z;
    Y[8] = 0.5462742152960396f * (x * x - y * y);
    Y[9]  = 0.5900435899266435f * y * (3.0f * x * x - y * y);
    Y[10] = 2.890611442640554f * x * y * z;
    Y[11] = 0.4570457994644658f * y * (5.0f * z * z - 1.0f);
    Y[12] = 0.3731763325901154f * z * (5.0f * z * z - 3.0f);
    Y[13] = 0.4570457994644658f * x * (5.0f * z * z - 1.0f);
    Y[14] = 1.445305721320277f * z * (x * x - y * y);
    Y[15] = 0.5900435899266435f * x * (x * x - 3.0f * y * y);
}

__device__ __forceinline__ void make_basis(float d, float* B) {
    float fc = 0.5f * (cosf(3.14159274101257324f * d / 5.0f) + 1.0f);
    #pragma unroll
    for (int i = 0; i < 8; i++) {
        float mu = (float)(5.0 * (double)i / 7.0);
        float t = (d - mu) / 0.625f;
        B[i] = expf(-0.5f * t * t) * fc;
    }
}

// ============================================================================
// Prep: zero counts + expand species embeddings
// ============================================================================
__global__ void k_prep(const int* __restrict__ species, const float* __restrict__ emb,
                       int n) {
    int i = blockIdx.x * blockDim.x + threadIdx.x;
    if (i >= n) return;
    g_count[i] = 0;
    int sp = __ldg(species + i);
    #pragma unroll
    for (int c = 0; c < 16; c++)
        g_embAt[i * 16 + c] = __ldg(emb + sp * 16 + c);
}

__global__ void k_count(const float* __restrict__ pos, const int* __restrict__ snd,
                        const int* __restrict__ rcv, int E) {
    int e = blockIdx.x * blockDim.x + threadIdx.x;
    if (e >= E) return;
    int s = __ldg(snd + e), r = __ldg(rcv + e);
    float d, ux, uy, uz;
    edge_geom(pos, s, r, d, ux, uy, uz);
    unsigned char live = (d < 5.0f) ? 1 : 0;
    g_live[e] = live;
    if (live) atomicAdd(&g_count[r], 1);
}

__global__ void k_scan(int n) {
    __shared__ int part[1024];
    int tid = threadIdx.x;
    int chunk = (n + 1023) >> 10;
    int beg = tid * chunk, end = min(beg + chunk, n);
    int s = 0;
    for (int i = beg; i < end; i++) s += g_count[i];
    part[tid] = s;
    __syncthreads();
    for (int off = 1; off < 1024; off <<= 1) {
        int v = (tid >= off) ? part[tid - off] : 0;
        __syncthreads();
        part[tid] += v;
        __syncthreads();
    }
    int run = (tid == 0) ? 0 : part[tid - 1];
    for (int i = beg; i < end; i++) {
        g_offsets[i] = run;
        g_cursor[i] = run;
        run += g_count[i];
    }
    if (tid == 1023) g_offsets[n] = part[1023];
}

__global__ void k_scatter(const float* __restrict__ pos, const int* __restrict__ snd,
                          const int* __restrict__ rcv, int E) {
    int e = blockIdx.x * blockDim.x + threadIdx.x;
    if (e >= E) return;
    if (!g_live[e]) return;
    int s = __ldg(snd + e), r = __ldg(rcv + e);
    float d, ux, uy, uz;
    edge_geom(pos, s, r, d, ux, uy, uz);
    int slot = atomicAdd(&g_cursor[r], 1);
    float Y[16]; make_sh(ux, uy, uz, Y);
    float B[8];  make_basis(d, B);
    g_sender[slot] = s;
    float4* o4 = (float4*)(g_sh + (size_t)slot * 16);
    o4[0] = make_float4(Y[0], Y[1], Y[2], Y[3]);
    o4[1] = make_float4(Y[4], Y[5], Y[6], Y[7]);
    o4[2] = make_float4(Y[8], Y[9], Y[10], Y[11]);
    o4[3] = make_float4(Y[12], Y[13], Y[14], Y[15]);
    float4* b4 = (float4*)(g_basis + (size_t)slot * 8);
    b4[0] = make_float4(B[0], B[1], B[2], B[3]);
    b4[1] = make_float4(B[4], B[5], B[6], B[7]);
}

// ============================================================================
// Phase A: first MP + CG self-interaction + embedding mul.
// One warp per atom; lane owns channels (lane, lane+32) as an f32x2 pair.
// Output layout: g_embedded[atom][k][si] (k-major).
// ============================================================================
__global__ __launch_bounds__(128, 4) void k_phaseA(int natoms, int ncs) {
    __shared__ ull sWinv2[64];                 // [n(2)][l*8+b]
    __shared__ __align__(16) ulonglong2 sSelf[MAXNZ];
    __shared__ __align__(16) ull sS2[4][512];  // per warp: o*32+lane
    for (int i = threadIdx.x; i < 64; i += 128) {
        int n = i >> 5, r = i & 31, l = r >> 3, b = r & 7;
        sWinv2[i] = pk2(g_Winv[l * 32 + b * 4 + n], g_Winv[l * 32 + b * 4 + n + 2]);
    }
    for (int i = threadIdx.x; i < ncs; i += 128) sSelf[i] = dSelf2[i];
    __syncthreads();

    int w = threadIdx.x >> 5, lane = threadIdx.x & 31;
    int a = blockIdx.x * 4 + w;
    if (a >= natoms) return;
    int c0 = lane & 15, n0 = lane >> 4;

    ull fa2[16];
    #pragma unroll
    for (int o = 0; o < 16; o++) fa2[o] = 0ULL;

    int beg = __ldg(&g_offsets[a]), end = __ldg(&g_offsets[a + 1]);
    for (int e = beg; e < end; e++) {
        float sh[16];
        {
            const float4* p4 = (const float4*)(g_sh + (size_t)e * 16);
            float4 t;
            t = __ldg(p4 + 0); sh[0] = t.x; sh[1] = t.y; sh[2] = t.z; sh[3] = t.w;
            t = __ldg(p4 + 1); sh[4] = t.x; sh[5] = t.y; sh[6] = t.z; sh[7] = t.w;
            t = __ldg(p4 + 2); sh[8] = t.x; sh[9] = t.y; sh[10] = t.z; sh[11] = t.w;
            t = __ldg(p4 + 3); sh[12] = t.x; sh[13] = t.y; sh[14] = t.z; sh[15] = t.w;
        }
        float B[8];
        {
            const float4* p4 = (const float4*)(g_basis + (size_t)e * 8);
            float4 t;
            t = __ldg(p4 + 0); B[0] = t.x; B[1] = t.y; B[2] = t.z; B[3] = t.w;
            t = __ldg(p4 + 1); B[4] = t.x; B[5] = t.y; B[6] = t.z; B[7] = t.w;
        }
        int s = __ldg(&g_sender[e]);
        float ev = __ldg(&g_embAt[s * 16 + c0]);
        ull ev2 = pk2(ev, ev);
        ull B2[8];
        #pragma unroll
        for (int b = 0; b < 8; b++) B2[b] = pk2(B[b], B[b]);
        ull r2[4];
        #pragma unroll
        for (int l = 0; l < 4; l++) {
            ull acc = 0ULL;
            #pragma unroll
            for (int b = 0; b < 8; b++)
                acc = fma2(B2[b], sWinv2[n0 * 32 + l * 8 + b], acc);
            r2[l] = mul2(acc, ev2);
        }
        #pragma unroll
        for (int o = 0; o < 16; o++)
            fa2[o] = fma2(pk2(sh[o], sh[o]), r2[lof(o)], fa2[o]);
    }
    #pragma unroll
    for (int o = 0; o < 16; o++) fa2[o] = mul2(fa2[o], HALF2);

    // stage packed feats for bilinear self-interaction
    ull* S = sS2[w];
    #pragma unroll
    for (int o = 0; o < 16; o++) S[o * 32 + lane] = fa2[o];
    __syncwarp();

    float embA = __ldg(&g_embAt[a * 16 + c0]);
    ull emb2 = pk2(embA, embA);
    float lo[16], hi[16];
    #pragma unroll
    for (int o = 0; o < 16; o++) {
        ull v2 = fa2[o];
        int b0 = cCsStart[o], b1 = cCsStart[o + 1];
        for (int t = b0; t < b1; t++) {
            ulonglong2 en = sSelf[t];
            unsigned m = (unsigned)en.x;
            int i32 = m & 0xFFFF, j32 = m >> 16;
            v2 = fma2(en.y, mul2(S[i32 + lane], S[j32 + lane]), v2);
        }
        v2 = mul2(v2, emb2);
        upk2(v2, lo[o], hi[o]);
    }
    // k-major stores: lane's channels at k0*16, k1*16 (16 contiguous each)
    float4* oa = (float4*)(g_embedded + (size_t)a * 1024 + lane * 16);
    float4* ob = (float4*)(g_embedded + (size_t)a * 1024 + (lane + 32) * 16);
    #pragma unroll
    for (int t = 0; t < 4; t++) {
        oa[t] = make_float4(lo[t * 4], lo[t * 4 + 1], lo[t * 4 + 2], lo[t * 4 + 3]);
        ob[t] = make_float4(hi[t * 4], hi[t * 4 + 1], hi[t * 4 + 2], hi[t * 4 + 3]);
    }
}

// ============================================================================
// Phase B: second MP + invariant contraction.
// One warp per atom; f32x2 packed channels; T duplicated f32x2 in smem.
// ============================================================================
__global__ __launch_bounds__(128, 4) void k_phaseB(const float* __restrict__ Weq,
                                                   int natoms, int nG, int nct) {
    __shared__ ull sWeq2[1024];                  // [L(4)][b(8)][lane(32)] packed (k,k+32)
    __shared__ int2 sTst[256];
    __shared__ int2 sTe[MAXNZ];
    __shared__ __align__(16) ull sScr[4][512];   // per warp: T pairs (256) / mp stage (512)
    __shared__ float sSh[4][16];
    for (int i = threadIdx.x; i < 1024; i += 128) {
        int L = i >> 8, r = i & 255, b = r >> 5, ln = r & 31;
        sWeq2[i] = pk2(__ldg(Weq + L * 512 + b * 64 + ln),
                       __ldg(Weq + L * 512 + b * 64 + 32 + ln));
    }
    for (int i = threadIdx.x; i < 256; i += 128) sTst[i] = dTstart[i];
    for (int i = threadIdx.x; i < nct; i += 128) sTe[i] = dTent[i];
    __syncthreads();

    int w = threadIdx.x >> 5, lane = threadIdx.x & 31;
    int a = blockIdx.x * 4 + w;
    if (a >= natoms) return;
    ull* Tw = sScr[w];
    float* Sh = sSh[w];

    ull m2[16];
    #pragma unroll
    for (int o = 0; o < 16; o++) m2[o] = 0ULL;

    int beg = __ldg(&g_offsets[a]), end = __ldg(&g_offsets[a + 1]);
    int s = (beg < end) ? __ldg(&g_sender[beg]) : 0;
    for (int e = beg; e < end; e++) {
        // neighbor gather (k-major: 8 LDG.128), issued early
        const float4* Xa = (const float4*)(g_embedded + (size_t)s * 1024 + lane * 16);
        const float4* Xb = (const float4*)(g_embedded + (size_t)s * 1024 + (lane + 32) * 16);
        float4 xa0 = __ldg(Xa + 0), xa1 = __ldg(Xa + 1), xa2 = __ldg(Xa + 2), xa3 = __ldg(Xa + 3);
        float4 xb0 = __ldg(Xb + 0), xb1 = __ldg(Xb + 1), xb2 = __ldg(Xb + 2), xb3 = __ldg(Xb + 3);
        float B[8];
        {
            const float4* p4 = (const float4*)(g_basis + (size_t)e * 8);
            float4 t;
            t = __ldg(p4 + 0); B[0] = t.x; B[1] = t.y; B[2] = t.z; B[3] = t.w;
            t = __ldg(p4 + 1); B[4] = t.x; B[5] = t.y; B[6] = t.z; B[7] = t.w;
        }
        if (lane < 16) Sh[lane] = __ldg(g_sh + (size_t)e * 16 + lane);
        int sn = (e + 1 < end) ? __ldg(&g_sender[e + 1]) : 0;
        // radial weights (packed)
        ull B2[8];
        #pragma unroll
        for (int b = 0; b < 8; b++) B2[b] = pk2(B[b], B[b]);
        ull q2[4];
        #pragma unroll
        for (int L = 0; L < 4; L++) {
            ull acc = 0ULL;
            #pragma unroll
            for (int b = 0; b < 8; b++)
                acc = fma2(B2[b], sWeq2[L * 256 + b * 32 + lane], acc);
            q2[L] = acc;
        }
        __syncwarp();
        // assemble T (duplicated f32x2 per entry), lane-parallel
        #pragma unroll
        for (int pi = 0; pi < 8; pi++) {
            int p = lane + pi * 32;
            int2 se = sTst[p];
            float v = 0.0f;
            for (int t = se.x; t < se.y; t++) {
                int2 en = sTe[t];
                v += __int_as_float(en.y) * Sh[en.x];
            }
            ((float2*)Tw)[p] = make_float2(v, v);
        }
        __syncwarp();
        // pack x
        ull x2[16];
        x2[0] = pk2(xa0.x, xb0.x); x2[1] = pk2(xa0.y, xb0.y);
        x2[2] = pk2(xa0.z, xb0.z); x2[3] = pk2(xa0.w, xb0.w);
        x2[4] = pk2(xa1.x, xb1.x); x2[5] = pk2(xa1.y, xb1.y);
        x2[6] = pk2(xa1.z, xb1.z); x2[7] = pk2(xa1.w, xb1.w);
        x2[8] = pk2(xa2.x, xb2.x); x2[9] = pk2(xa2.y, xb2.y);
        x2[10] = pk2(xa2.z, xb2.z); x2[11] = pk2(xa2.w, xb2.w);
        x2[12] = pk2(xa3.x, xb3.x); x2[13] = pk2(xa3.y, xb3.y);
        x2[14] = pk2(xa3.z, xb3.z); x2[15] = pk2(xa3.w, xb3.w);
        // dense 16x16 contraction (f32x2)
        #pragma unroll
        for (int o = 0; o < 16; o++) {
            ull u = 0ULL;
            const ulonglong2* Trow = (const ulonglong2*)(Tw + o * 16);
            #pragma unroll
            for (int t = 0; t < 8; t++) {
                ulonglong2 tv = Trow[t];
                u = fma2(tv.x, x2[2 * t], u);
                u = fma2(tv.y, x2[2 * t + 1], u);
            }
            m2[o] = fma2(q2[lof(o)], u, m2[o]);
        }
        s = sn;
        __syncwarp();
    }

    // mp = 0.5*m ; stage for invariant contraction
    #pragma unroll
    for (int o = 0; o < 16; o++) Tw[o * 32 + lane] = mul2(m2[o], HALF2);
    __syncwarp();
    ull inv2 = Tw[lane];                         // mp[0][0]
    for (int t = 0; t < nG; t++) {
        int2 en = __ldg(&dG[t]);
        unsigned m = (unsigned)en.x;
        int i32 = m & 0xFFFF, j32 = m >> 16;
        unsigned vb = (unsigned)en.y;
        ull cv2 = ((ull)vb << 32) | vb;
        inv2 = fma2(cv2, mul2(Tw[i32 + lane], Tw[j32 + lane]), inv2);
    }
    float vlo, vhi;
    upk2(inv2, vlo, vhi);
    g_inv[(size_t)a * 64 + lane] = vlo;
    g_inv[(size_t)a * 64 + 32 + lane] = vhi;
}

// ============================================================================
// MLP per atom (one warp per atom)
// ============================================================================
__global__ __launch_bounds__(128) void k_mlp(const float* __restrict__ W1,
                                             const float* __restrict__ W2,
                                             const float* __restrict__ wl,
                                             int natoms) {
    __shared__ float sW1[4096], sW2[4096], sWl[64];
    for (int i = threadIdx.x; i < 4096; i += 128) {
        sW1[i] = __ldg(W1 + i);
        sW2[i] = __ldg(W2 + i);
    }
    if (threadIdx.x < 64) sWl[threadIdx.x] = __ldg(wl + threadIdx.x);
    __syncthreads();

    int w = threadIdx.x >> 5, lane = threadIdx.x & 31;
    int a = blockIdx.x * 4 + w;
    if (a >= natoms) return;

    float i0 = g_inv[(size_t)a * 64 + lane];
    float i1 = g_inv[(size_t)a * 64 + 32 + lane];
    float h0 = 0.0f, h1 = 0.0f;
    #pragma unroll
    for (int j = 0; j < 64; j++) {
        float bj = __shfl_sync(0xffffffffu, (j < 32) ? i0 : i1, j & 31);
        h0 += bj * sW1[j * 64 + lane];
        h1 += bj * sW1[j * 64 + 32 + lane];
    }
    h0 = h0 / (1.0f + expf(-h0));
    h1 = h1 / (1.0f + expf(-h1));
    float g0 = 0.0f, g1 = 0.0f;
    #pragma unroll
    for (int j = 0; j < 64; j++) {
        float bj = __shfl_sync(0xffffffffu, (j < 32) ? h0 : h1, j & 31);
        g0 += bj * sW2[j * 64 + lane];
        g1 += bj * sW2[j * 64 + 32 + lane];
    }
    g0 = g0 / (1.0f + expf(-g0));
    g1 = g1 / (1.0f + expf(-g1));
    float p = g0 * sWl[lane] + g1 * sWl[32 + lane];
    #pragma unroll
    for (int off = 16; off; off >>= 1) p += __shfl_xor_sync(0xffffffffu, p, off);
    if (lane == 0) g_atomE[a] = p;
}

__global__ void k_reduce(float* __restrict__ out, int n) {
    __shared__ double sred[1024];
    double s = 0.0;
    for (int i = threadIdx.x; i < n; i += 1024) s += (double)g_atomE[i];
    sred[threadIdx.x] = s;
    __syncthreads();
    for (int st = 512; st; st >>= 1) {
        if (threadIdx.x < st) sred[threadIdx.x] += sred[threadIdx.x + st];
        __syncthreads();
    }
    if (threadIdx.x == 0) out[0] = (float)sred[0];
}

// ============================================================================
// Host: exact port of the reference Clebsch-Gordan / real-SH coupling tables
// ============================================================================
namespace phace_host {

using cd = std::complex<double>;

static double hfact(int n) { double r = 1; for (int i = 2; i <= n; i++) r *= i; return r; }

static double hcg(int j1, int m1, int j2, int m2, int J, int M) {
    if (m1 + m2 != M || J < std::abs(j1 - j2) || J > j1 + j2) return 0.0;
    double pref = std::sqrt((2 * J + 1) * hfact(J + j1 - j2) * hfact(J - j1 + j2) *
                            hfact(j1 + j2 - J) / hfact(j1 + j2 + J + 1));
    pref *= std::sqrt(hfact(J + M) * hfact(J - M) * hfact(j1 - m1) * hfact(j1 + m1) *
                      hfact(j2 - m2) * hfact(j2 + m2));
    double s = 0.0;
    for (int k = 0; k <= j1 + j2 - J; k++) {
        int d0 = k, d1 = j1 + j2 - J - k, d2 = j1 - m1 - k, d3 = j2 + m2 - k;
        int d4 = J - j2 + m1 + k, d5 = J - j1 - m2 + k;
        if (d0 < 0 || d1 < 0 || d2 < 0 || d3 < 0 || d4 < 0 || d5 < 0) continue;
        double den = hfact(d0) * hfact(d1) * hfact(d2) * hfact(d3) * hfact(d4) * hfact(d5);
        s += ((k & 1) ? -1.0 : 1.0) / den;
    }
    return pref * s;
}

static void hureal(int l, cd U[7][7]) {
    for (int i = 0; i < 7; i++)
        for (int j = 0; j < 7; j++) U[i][j] = cd(0.0, 0.0);
    U[l][l] = cd(1.0, 0.0);
    const double is2 = 1.0 / std::sqrt(2.0);
    for (int m = 1; m <= l; m++) {
        double sg = (m & 1) ? -1.0 : 1.0;
        U[l + m][l + m] = cd(sg * is2, 0.0);
        U[l + m][l - m] = cd(is2, 0.0);
        U[l - m][l - m] = cd(0.0, is2);
        U[l - m][l + m] = cd(0.0, -is2 * sg);
    }
}

static void hrealcg(int l1, int l2, int L, float out[7][7][7]) {
    cd U1[7][7], U2[7][7], U3[7][7];
    hureal(l1, U1); hureal(l2, U2); hureal(L, U3);
    int d1 = 2 * l1 + 1, d2 = 2 * l2 + 1, d3 = 2 * L + 1;
    static cd T[7][7][7];
    double sre = 0.0, sim = 0.0;
    for (int a = 0; a < d1; a++)
        for (int b = 0; b < d2; b++)
            for (int c = 0; c < d3; c++) {
                cd acc(0.0, 0.0);
                for (int m = 0; m < d1; m++) {
                    cd u1 = U1[a][m];
                    if (u1.real() == 0.0 && u1.imag() == 0.0) continue;
                    for (int n = 0; n < d2; n++) {
                        cd u2 = U2[b][n];
                        if (u2.real() == 0.0 && u2.imag() == 0.0) continue;
                        for (int o = 0; o < d3; o++) {
                            cd u3 = std::conj(U3[c][o]);
                            if (u3.real() == 0.0 && u3.imag() == 0.0) continue;
                            double cgv = hcg(l1, m - l1, l2, n - l2, L, o - L);
                            if (cgv != 0.0) acc += u1 * u2 * u3 * cgv;
                        }
                    }
                }
                T[a][b][c] = acc;
                sre += std::abs(acc.real());
                sim += std::abs(acc.imag());
            }
    bool usere = (sre >= sim);
    for (int a = 0; a < d1; a++)
        for (int b = 0; b < d2; b++)
            for (int c = 0; c < d3; c++)
                out[a][b][c] = (float)(usere ? T[a][b][c].real() : T[a][b][c].imag());
}

static int f2i(float v) { int r; std::memcpy(&r, &v, 4); return r; }
static unsigned long long fdup(float v) {
    unsigned u; std::memcpy(&u, &v, 4);
    return ((unsigned long long)u << 32) | u;
}

struct HostTables {
    int  cs_start[17]; ulonglong2 self[MAXNZ]; int ncs;
    int2 tstart[256];  int2 tent[MAXNZ]; int nct;
    int2 g[MAXG];      int ng;
};

static void build_tables(HostTables& H) {
    const int OFF[4] = {0, 1, 4, 9};
    struct E3 { short i, j; float v; };
    struct E2 { short a; float v; };
    std::vector<E3> so[16];
    std::vector<E2> tp[256];
    H.ng = 0;
    static float C[7][7][7];
    for (int l1 = 0; l1 < 4; l1++)
        for (int l2 = 0; l2 < 4; l2++) {
            int Llo = std::abs(l1 - l2), Lhi = std::min(l1 + l2, 3);
            for (int L = Llo; L <= Lhi; L++) {
                hrealcg(l1, l2, L, C);
                for (int a = 0; a < 2 * l1 + 1; a++)
                    for (int b = 0; b < 2 * l2 + 1; b++)
                        for (int c = 0; c < 2 * L + 1; c++) {
                            float v = C[a][b][c];
                            if (std::fabs(v) < 1e-7f) continue;
                            int o = OFF[L] + c, si = OFF[l2] + b, sa = OFF[l1] + a;
                            so[o].push_back({(short)sa, (short)si, v});
                            tp[o * 16 + si].push_back({(short)sa, v});
                            if (L == 0 && l1 == l2 && H.ng < MAXG) {
                                H.g[H.ng].x = (sa * 32) | ((si * 32) << 16);
                                H.g[H.ng].y = f2i(v);
                                H.ng++;
                            }
                        }
            }
        }
    int idx = 0;
    for (int o = 0; o < 16; o++) {
        H.cs_start[o] = idx;
        for (auto& e : so[o]) {
            if (idx >= MAXNZ) break;
            H.self[idx].x = (unsigned long long)((e.i * 32) | ((e.j * 32) << 16));
            H.self[idx].y = fdup(e.v);
            idx++;
        }
    }
    H.cs_start[16] = idx; H.ncs = idx;
    idx = 0;
    for (int p = 0; p < 256; p++) {
        H.tstart[p].x = idx;
        for (auto& e : tp[p]) {
            if (idx >= MAXNZ) break;
            H.tent[idx].x = e.a;
            H.tent[idx].y = f2i(e.v);
            idx++;
        }
        H.tstart[p].y = idx;
    }
    H.nct = idx;
}

} // namespace phace_host

// ============================================================================
// kernel_launch
// ============================================================================
extern "C" void kernel_launch(void* const* d_in, const int* in_sizes, int n_in,
                              void* d_out, int out_size) {
    const float* pos     = (const float*)d_in[0];
    const float* emb     = (const float*)d_in[1];
    const float* Winv    = (const float*)d_in[2];
    const float* Weq     = (const float*)d_in[3];
    const float* W1      = (const float*)d_in[4];
    const float* W2      = (const float*)d_in[5];
    const float* wl      = (const float*)d_in[6];
    const int*   species = (const int*)d_in[7];
    const int*   snd     = (const int*)d_in[8];
    const int*   rcv     = (const int*)d_in[9];
    int N = in_sizes[7];
    int E = in_sizes[8];
    if (N > MAXN_AT) N = MAXN_AT;
    if (E > MAXE_ED) E = MAXE_ED;

    static phace_host::HostTables H;   // static: must persist for graph replays
    phace_host::build_tables(H);       // deterministic, rebuilt every call

    cudaMemcpyToSymbolAsync(cCsStart, H.cs_start, sizeof(int) * 17, 0, cudaMemcpyHostToDevice, 0);
    cudaMemcpyToSymbolAsync(dSelf2, H.self, sizeof(ulonglong2) * H.ncs, 0, cudaMemcpyHostToDevice, 0);
    cudaMemcpyToSymbolAsync(dTstart, H.tstart, sizeof(int2) * 256, 0, cudaMemcpyHostToDevice, 0);
    cudaMemcpyToSymbolAsync(dTent, H.tent, sizeof(int2) * H.nct, 0, cudaMemcpyHostToDevice, 0);
    cudaMemcpyToSymbolAsync(dG, H.g, sizeof(int2) * (H.ng > 0 ? H.ng : 1), 0, cudaMemcpyHostToDevice, 0);
    cudaMemcpyToSymbolAsync(g_Winv, Winv, 128 * sizeof(float), 0, cudaMemcpyDeviceToDevice, 0);

    k_prep<<<(N + 127) / 128, 128>>>(species, emb, N);
    k_count<<<(E + 255) / 256, 256>>>(pos, snd, rcv, E);
    k_scan<<<1, 1024>>>(N);
    k_scatter<<<(E + 255) / 256, 256>>>(pos, snd, rcv, E);
    k_phaseA<<<(N + 3) / 4, 128>>>(N, H.ncs);
    k_phaseB<<<(N + 3) / 4, 128>>>(Weq, N, H.ng, H.nct);
    k_mlp<<<(N + 3) / 4, 128>>>(W1, W2, wl, N);
    k_reduce<<<1, 1024>>>((float*)d_out, N);
}